// round 4
// baseline (speedup 1.0000x reference)
#include <cuda_runtime.h>

// WENO-Z 1-D periodic, B=16 x N=2^20 fp32.
// fma-bound. Difference-form algebra: shared R/c per d2-index collapse the
// three smoothness indicators; odd alignments via ALU movs, not fma recompute.

#define N_ELEMS   1048576
#define N_MASK    (N_ELEMS - 1)
#define TPB       128
#define VEC       8
#define TILE      (TPB * VEC)    // 1024

#define EPS 1e-13f

typedef unsigned long long u64;

__device__ __forceinline__ u64 pk(float lo, float hi) {
    u64 r; asm("mov.b64 %0, {%1, %2};" : "=l"(r) : "f"(lo), "f"(hi)); return r;
}
__device__ __forceinline__ void upk(float& lo, float& hi, u64 v) {
    asm("mov.b64 {%0, %1}, %2;" : "=f"(lo), "=f"(hi) : "l"(v));
}
__device__ __forceinline__ float hif(u64 v) { float lo, hi; upk(lo, hi, v); return hi; }
__device__ __forceinline__ u64 shifted(u64 a, u64 b) {   // (hi(a), lo(b)) — ALU movs only
    float alo, ahi, blo, bhi; upk(alo, ahi, a); upk(blo, bhi, b); return pk(ahi, blo);
}
__device__ __forceinline__ u64 f2mul(u64 a, u64 b) {
    u64 d; asm("mul.rn.f32x2 %0, %1, %2;" : "=l"(d) : "l"(a), "l"(b)); return d;
}
__device__ __forceinline__ u64 f2add(u64 a, u64 b) {
    u64 d; asm("add.rn.f32x2 %0, %1, %2;" : "=l"(d) : "l"(a), "l"(b)); return d;
}
__device__ __forceinline__ u64 f2fma(u64 a, u64 b, u64 c) {
    u64 d; asm("fma.rn.f32x2 %0, %1, %2, %3;" : "=l"(d) : "l"(a), "l"(b), "l"(c)); return d;
}
__device__ __forceinline__ u64 f2abs(u64 a) { return a & 0x7FFFFFFF7FFFFFFFULL; }

__global__ void __launch_bounds__(TPB) weno_z_kernel(
    const float* __restrict__ x, float* __restrict__ out)
{
    __shared__ __align__(16) float s[TILE + 16];
    // s[4 + k] = x[start + k] for k in [-4, TILE+8)

    const int b     = blockIdx.y;
    const int start = blockIdx.x * TILE;
    const float* xb = x + (size_t)b * N_ELEMS;
    const int t     = threadIdx.x;

    float4 va = *reinterpret_cast<const float4*>(xb + start + t * VEC);
    float4 vb = *reinterpret_cast<const float4*>(xb + start + t * VEC + 4);
    *reinterpret_cast<float4*>(&s[4 + t * VEC])     = va;
    *reinterpret_cast<float4*>(&s[4 + t * VEC + 4]) = vb;

    if (t < 4) {
        s[t] = xb[(start - 4 + t) & N_MASK];               // left halo
    } else if (t < 12) {
        s[TILE + t] = xb[(start + TILE + t - 4) & N_MASK]; // right halo
    }
    __syncthreads();

    // p[k] = x[n0 - 4 + k], k = 0..12 ; n0 = start + t*8 ; outputs at m = 4..11
    float p[13];
    float4 f0  = *reinterpret_cast<const float4*>(&s[t * VEC]);
    float4 f1  = *reinterpret_cast<const float4*>(&s[t * VEC + 4]);
    float4 f2v = *reinterpret_cast<const float4*>(&s[t * VEC + 8]);
    p[0]=f0.x;  p[1]=f0.y;  p[2]=f0.z;  p[3]=f0.w;
    p[4]=f1.x;  p[5]=f1.y;  p[6]=f1.z;  p[7]=f1.w;
    p[8]=f2v.x; p[9]=f2v.y; p[10]=f2v.z; p[11]=f2v.w;
    p[12] = s[t * VEC + 12];

    const u64 Cm1  = pk(-1.0f, -1.0f);
    const u64 C2   = pk(2.0f, 2.0f);
    const u64 C3   = pk(3.0f, 3.0f);
    const u64 C43  = pk(4.0f/3.0f, 4.0f/3.0f);
    const u64 C05  = pk(0.5f, 0.5f);
    const u64 Cm05 = pk(-0.5f, -0.5f);
    const u64 C13  = pk(1.0f/3.0f, 1.0f/3.0f);
    const u64 Cm16 = pk(-1.0f/6.0f, -1.0f/6.0f);
    const u64 Ceps = pk(EPS, EPS);
    const u64 Cd0  = pk(0.1f, 0.1f);
    const u64 Cd1  = pk(0.6f, 0.6f);
    const u64 Cd2  = pk(0.3f, 0.3f);

    // Even-aligned packed stages, j = 1..5 stored at idx j-1:
    //   E1[j] = (d1[2j],   d1[2j+1])    d1[k] = p[k]-p[k-1]
    //   O1[j] = (d1[2j+1], d1[2j+2])    (realigned, ALU movs)
    //   E2[j] = (d2[2j],   d2[2j+1])    d2[k] = d1[k+1]-d1[k]
    //   m2 = E2^2 ; R = E1^2 + 4/3*E2^2 + eps ; c = E1*E2
    u64 E1[5], O1[5], E2[5], R[5], c[5], m2[5];

    #pragma unroll
    for (int i = 0; i < 5; i++) {
        u64 ppe = pk(p[2*i + 2], p[2*i + 3]);
        u64 ppo = pk(p[2*i + 1], p[2*i + 2]);
        E1[i] = f2fma(ppo, Cm1, ppe);
    }
    const float d1_12 = p[12] - p[11];

    #pragma unroll
    for (int i = 0; i < 4; i++) O1[i] = shifted(E1[i], E1[i + 1]);
    O1[4] = pk(hif(E1[4]), d1_12);

    #pragma unroll
    for (int i = 0; i < 5; i++) {
        E2[i] = f2fma(E1[i], Cm1, O1[i]);
        m2[i] = f2mul(E2[i], E2[i]);
        R[i]  = f2fma(E1[i], E1[i], f2fma(m2[i], C43, Ceps));
        c[i]  = f2mul(E1[i], E2[i]);
    }

    float o[VEC];

    #pragma unroll
    for (int q = 0; q < 4; q++) {
        const int a1 = q, a2 = q + 1;   // j = q+1, q+2

        // smoothness indicators (eps folded into R)
        const u64 IS0 = f2fma(c[a1], C3, f2fma(m2[a1], C2, R[a1]));
        const u64 IS2 = f2fma(c[a2], Cm1, R[a2]);
        const u64 IS1 = f2add(shifted(R[a1], R[a2]), shifted(c[a1], c[a2]));

        const u64 T5 = f2abs(f2fma(IS0, Cm1, IS2));

        const u64 t0 = f2add(IS0, T5);
        const u64 t1 = f2add(IS1, T5);
        const u64 t2 = f2add(IS2, T5);
        const u64 g0 = f2mul(Cd0, t0);
        const u64 g1 = f2mul(Cd1, t1);
        const u64 g2 = f2mul(Cd2, t2);
        const u64 e01 = f2mul(IS0, IS1);
        const u64 e02 = f2mul(IS0, IS2);
        const u64 e12 = f2mul(IS1, IS2);
        const u64 w0 = f2mul(g0, e12);
        const u64 w1 = f2mul(g1, e02);
        const u64 w2 = f2mul(g2, e01);

        // candidates: G = x2 + d1[m-1]/2 shared by P0,P1
        const u64 X2 = pk(p[2*q + 3], p[2*q + 4]);
        const u64 X3 = pk(p[2*q + 4], p[2*q + 5]);
        const u64 G  = f2fma(O1[a1], C05, X2);
        const u64 P0 = f2fma(E2[a1], C13, G);
        const u64 P1 = f2fma(shifted(E2[a1], E2[a2]), C13, G);
        const u64 P2 = f2fma(E2[a2], Cm16, f2fma(E1[a2], Cm05, X3));

        const u64 num = f2fma(w2, P2, f2fma(w1, P1, f2mul(w0, P0)));
        const u64 den = f2add(f2add(w0, w1), w2);

        float n0, n1, d0, d1v;
        upk(n0, n1, num); upk(d0, d1v, den);
        o[2*q]     = __fdividef(n0, d0);
        o[2*q + 1] = __fdividef(n1, d1v);
    }

    float* ob = out + (size_t)b * N_ELEMS + start + t * VEC;
    *reinterpret_cast<float4*>(ob)     = make_float4(o[0], o[1], o[2], o[3]);
    *reinterpret_cast<float4*>(ob + 4) = make_float4(o[4], o[5], o[6], o[7]);
}

extern "C" void kernel_launch(void* const* d_in, const int* in_sizes, int n_in,
                              void* d_out, int out_size)
{
    const float* x = (const float*)d_in[0];
    float* out = (float*)d_out;
    const int total = in_sizes[0];
    const int batches = total / N_ELEMS;

    dim3 grid(N_ELEMS / TILE, batches);
    weno_z_kernel<<<grid, TPB>>>(x, out);
}

// round 5
// speedup vs baseline: 1.0621x; 1.0621x over previous
#include <cuda_runtime.h>

// WENO-Z 1-D periodic, B=16 x N=2^20 fp32.
// No shared memory: stencil windows read directly via aligned LDG.128
// (L1/L2 dedup the 5-element overlaps). Difference-form packed f32x2 math.

#define N_ELEMS   1048576
#define N_MASK    (N_ELEMS - 1)
#define TPB       128
#define VEC       8
#define TILE      (TPB * VEC)    // 1024

#define EPS 1e-13f

typedef unsigned long long u64;

__device__ __forceinline__ u64 pk(float lo, float hi) {
    u64 r; asm("mov.b64 %0, {%1, %2};" : "=l"(r) : "f"(lo), "f"(hi)); return r;
}
__device__ __forceinline__ void upk(float& lo, float& hi, u64 v) {
    asm("mov.b64 {%0, %1}, %2;" : "=f"(lo), "=f"(hi) : "l"(v));
}
__device__ __forceinline__ float hif(u64 v) { float lo, hi; upk(lo, hi, v); return hi; }
__device__ __forceinline__ u64 shifted(u64 a, u64 b) {   // (hi(a), lo(b)) — ALU movs only
    float alo, ahi, blo, bhi; upk(alo, ahi, a); upk(blo, bhi, b); return pk(ahi, blo);
}
__device__ __forceinline__ u64 f2mul(u64 a, u64 b) {
    u64 d; asm("mul.rn.f32x2 %0, %1, %2;" : "=l"(d) : "l"(a), "l"(b)); return d;
}
__device__ __forceinline__ u64 f2add(u64 a, u64 b) {
    u64 d; asm("add.rn.f32x2 %0, %1, %2;" : "=l"(d) : "l"(a), "l"(b)); return d;
}
__device__ __forceinline__ u64 f2fma(u64 a, u64 b, u64 c) {
    u64 d; asm("fma.rn.f32x2 %0, %1, %2, %3;" : "=l"(d) : "l"(a), "l"(b), "l"(c)); return d;
}
__device__ __forceinline__ u64 f2abs(u64 a) { return a & 0x7FFFFFFF7FFFFFFFULL; }

__global__ void __launch_bounds__(TPB) weno_z_kernel(
    const float* __restrict__ x, float* __restrict__ out)
{
    const int b     = blockIdx.y;
    const int start = blockIdx.x * TILE;
    const float* xb = x + (size_t)b * N_ELEMS;
    const int t     = threadIdx.x;

    const int n0 = start + t * VEC;          // first output index for this thread
    // p[k] = x[(n0 - 4 + k) & MASK], k = 0..12 ; outputs at m = 4..11
    // (n0 - 4) is a multiple of 4 -> masked bases stay 16B-aligned.
    const int base = n0 - 4;
    float4 f0  = *reinterpret_cast<const float4*>(xb + ((base)      & N_MASK));
    float4 f1  = *reinterpret_cast<const float4*>(xb + ((base + 4)  & N_MASK));
    float4 f2v = *reinterpret_cast<const float4*>(xb + ((base + 8)  & N_MASK));
    float p12  = xb[(base + 12) & N_MASK];

    float p[13];
    p[0]=f0.x;  p[1]=f0.y;  p[2]=f0.z;  p[3]=f0.w;
    p[4]=f1.x;  p[5]=f1.y;  p[6]=f1.z;  p[7]=f1.w;
    p[8]=f2v.x; p[9]=f2v.y; p[10]=f2v.z; p[11]=f2v.w;
    p[12] = p12;

    const u64 Cm1  = pk(-1.0f, -1.0f);
    const u64 C2   = pk(2.0f, 2.0f);
    const u64 C3   = pk(3.0f, 3.0f);
    const u64 C43  = pk(4.0f/3.0f, 4.0f/3.0f);
    const u64 C05  = pk(0.5f, 0.5f);
    const u64 Cm05 = pk(-0.5f, -0.5f);
    const u64 C13  = pk(1.0f/3.0f, 1.0f/3.0f);
    const u64 Cm16 = pk(-1.0f/6.0f, -1.0f/6.0f);
    const u64 Ceps = pk(EPS, EPS);
    const u64 Cd0  = pk(0.1f, 0.1f);
    const u64 Cd1  = pk(0.6f, 0.6f);
    const u64 Cd2  = pk(0.3f, 0.3f);

    // Even-aligned packed stages, j = 1..5 stored at idx j-1:
    //   E1[j] = (d1[2j],   d1[2j+1])    d1[k] = p[k]-p[k-1]
    //   O1[j] = (d1[2j+1], d1[2j+2])    (realigned, ALU movs)
    //   E2[j] = (d2[2j],   d2[2j+1])    d2[k] = d1[k+1]-d1[k]
    //   m2 = E2^2 ; R = E1^2 + 4/3*E2^2 + eps ; c = E1*E2
    u64 E1[5], O1[5], E2[5], R[5], c[5], m2[5];

    #pragma unroll
    for (int i = 0; i < 5; i++) {
        u64 ppe = pk(p[2*i + 2], p[2*i + 3]);
        u64 ppo = pk(p[2*i + 1], p[2*i + 2]);
        E1[i] = f2fma(ppo, Cm1, ppe);
    }
    const float d1_12 = p[12] - p[11];

    #pragma unroll
    for (int i = 0; i < 4; i++) O1[i] = shifted(E1[i], E1[i + 1]);
    O1[4] = pk(hif(E1[4]), d1_12);

    #pragma unroll
    for (int i = 0; i < 5; i++) {
        E2[i] = f2fma(E1[i], Cm1, O1[i]);
        m2[i] = f2mul(E2[i], E2[i]);
        R[i]  = f2fma(E1[i], E1[i], f2fma(m2[i], C43, Ceps));
        c[i]  = f2mul(E1[i], E2[i]);
    }

    float o[VEC];

    #pragma unroll
    for (int q = 0; q < 4; q++) {
        const int a1 = q, a2 = q + 1;   // j = q+1, q+2

        // smoothness indicators (eps folded into R)
        const u64 IS0 = f2fma(c[a1], C3, f2fma(m2[a1], C2, R[a1]));
        const u64 IS2 = f2fma(c[a2], Cm1, R[a2]);
        const u64 IS1 = f2add(shifted(R[a1], R[a2]), shifted(c[a1], c[a2]));

        const u64 T5 = f2abs(f2fma(IS0, Cm1, IS2));

        const u64 t0 = f2add(IS0, T5);
        const u64 t1 = f2add(IS1, T5);
        const u64 t2 = f2add(IS2, T5);
        const u64 g0 = f2mul(Cd0, t0);
        const u64 g1 = f2mul(Cd1, t1);
        const u64 g2 = f2mul(Cd2, t2);
        const u64 e01 = f2mul(IS0, IS1);
        const u64 e02 = f2mul(IS0, IS2);
        const u64 e12 = f2mul(IS1, IS2);
        const u64 w0 = f2mul(g0, e12);
        const u64 w1 = f2mul(g1, e02);
        const u64 w2 = f2mul(g2, e01);

        // candidates: G = x2 + d1[m-1]/2 shared by P0,P1
        const u64 X2 = pk(p[2*q + 3], p[2*q + 4]);
        const u64 X3 = pk(p[2*q + 4], p[2*q + 5]);
        const u64 G  = f2fma(O1[a1], C05, X2);
        const u64 P0 = f2fma(E2[a1], C13, G);
        const u64 P1 = f2fma(shifted(E2[a1], E2[a2]), C13, G);
        const u64 P2 = f2fma(E2[a2], Cm16, f2fma(E1[a2], Cm05, X3));

        const u64 num = f2fma(w2, P2, f2fma(w1, P1, f2mul(w0, P0)));
        const u64 den = f2add(f2add(w0, w1), w2);

        float n0f, n1f, d0f, d1f;
        upk(n0f, n1f, num); upk(d0f, d1f, den);
        o[2*q]     = __fdividef(n0f, d0f);
        o[2*q + 1] = __fdividef(n1f, d1f);
    }

    float* ob = out + (size_t)b * N_ELEMS + n0;
    *reinterpret_cast<float4*>(ob)     = make_float4(o[0], o[1], o[2], o[3]);
    *reinterpret_cast<float4*>(ob + 4) = make_float4(o[4], o[5], o[6], o[7]);
}

extern "C" void kernel_launch(void* const* d_in, const int* in_sizes, int n_in,
                              void* d_out, int out_size)
{
    const float* x = (const float*)d_in[0];
    float* out = (float*)d_out;
    const int total = in_sizes[0];
    const int batches = total / N_ELEMS;

    dim3 grid(N_ELEMS / TILE, batches);
    weno_z_kernel<<<grid, TPB>>>(x, out);
}